// round 9
// baseline (speedup 1.0000x reference)
#include <cuda_runtime.h>
#include <cuda_fp16.h>
#include <cstdint>

// ---------------------------------------------------------------- constants
#define D_Z     1024
#define D_MODEL 4096
#define M_ROWS  16384
#define EPS     1e-5f

#define BM 128
#define BN 64
#define BK 32
#define KITERS (D_Z / BK)      // 32
#define STAGES 3

#define LDA 40                  // 32 + 8 pad (fp16): conflict-free ldmatrix
#define LDB 72                  // 64 + 8 pad
#define A_STAGE_B (BM * LDA * 2)          // 10240 B
#define B_STAGE_B (BK * LDB * 2)          // 4608 B
#define STAGE_B   (A_STAGE_B + B_STAGE_B) // 14848 B
#define SMEM_TOTAL (STAGES * STAGE_B)     // 44544 B -> 4 CTAs/SM

#define WCONV_BLOCKS 1024

// scratch (allocation-free rule: device globals)
__device__ __half g_zn[(size_t)M_ROWS * D_Z];     // LN output fp16 [M,K]
__device__ __half g_wb[(size_t)D_Z * D_MODEL];    // W fp16 [K,N]

// ---------------------------------------------------------------- K1: merged prep
__global__ __launch_bounds__(256) void prep_kernel(const float* __restrict__ z,
                                                   const float* __restrict__ gamma,
                                                   const float* __restrict__ beta,
                                                   const float* __restrict__ W) {
    int blk = blockIdx.x;
    int t   = threadIdx.x;

    if (blk >= M_ROWS) {
        size_t base = (size_t)(blk - M_ROWS) * 1024 + t;
        __half2* dst = (__half2*)g_wb;
        #pragma unroll
        for (int u = 0; u < 4; u++) {
            size_t i = base + (size_t)u * 256;
            float4 v = ((const float4*)W)[i];
            dst[i * 2 + 0] = __floats2half2_rn(v.x, v.y);
            dst[i * 2 + 1] = __floats2half2_rn(v.z, v.w);
        }
        return;
    }

    int row = blk, lane = t & 31, wid = t >> 5;
    const float4* zp = (const float4*)(z + (size_t)row * D_Z);
    float4 v = zp[t];

    float s  = v.x + v.y + v.z + v.w;
    float ss = v.x * v.x + v.y * v.y + v.z * v.z + v.w * v.w;
    #pragma unroll
    for (int o = 16; o > 0; o >>= 1) {
        s  += __shfl_xor_sync(0xffffffffu, s, o);
        ss += __shfl_xor_sync(0xffffffffu, ss, o);
    }
    __shared__ float sbuf[8], ssbuf[8], smu, srstd;
    if (lane == 0) { sbuf[wid] = s; ssbuf[wid] = ss; }
    __syncthreads();
    if (t == 0) {
        float S = 0.f, SS = 0.f;
        #pragma unroll
        for (int i = 0; i < 8; i++) { S += sbuf[i]; SS += ssbuf[i]; }
        float mu  = S * (1.0f / D_Z);
        float var = SS * (1.0f / D_Z) - mu * mu;
        smu = mu; srstd = rsqrtf(var + EPS);
    }
    __syncthreads();
    float mu = smu, rstd = srstd;

    float4 g = ((const float4*)gamma)[t];
    float4 b = ((const float4*)beta)[t];
    float o0 = (v.x - mu) * rstd * g.x + b.x;
    float o1 = (v.y - mu) * rstd * g.y + b.y;
    float o2 = (v.z - mu) * rstd * g.z + b.z;
    float o3 = (v.w - mu) * rstd * g.w + b.w;

    __half2* dst = (__half2*)(g_zn + (size_t)row * D_Z);
    dst[t * 2 + 0] = __floats2half2_rn(o0, o1);
    dst[t * 2 + 1] = __floats2half2_rn(o2, o3);
}

// ---------------------------------------------------------------- PTX wrappers
__device__ __forceinline__ void ldmatrix_x4(uint32_t r[4], uint32_t addr) {
    asm volatile("ldmatrix.sync.aligned.m8n8.x4.shared.b16 {%0,%1,%2,%3}, [%4];\n"
                 : "=r"(r[0]), "=r"(r[1]), "=r"(r[2]), "=r"(r[3]) : "r"(addr));
}
__device__ __forceinline__ void ldmatrix_b(uint32_t& b00, uint32_t& b01,
                                           uint32_t& b10, uint32_t& b11, uint32_t addr) {
    asm volatile("ldmatrix.sync.aligned.m8n8.x4.trans.shared.b16 {%0,%1,%2,%3}, [%4];\n"
                 : "=r"(b00), "=r"(b01), "=r"(b10), "=r"(b11) : "r"(addr));
}
__device__ __forceinline__ void mma_16816(float c[4], const uint32_t a[4],
                                          uint32_t b0, uint32_t b1) {
    asm volatile("mma.sync.aligned.m16n8k16.row.col.f32.f16.f16.f32 "
                 "{%0,%1,%2,%3}, {%4,%5,%6,%7}, {%8,%9}, {%0,%1,%2,%3};\n"
                 : "+f"(c[0]), "+f"(c[1]), "+f"(c[2]), "+f"(c[3])
                 : "r"(a[0]), "r"(a[1]), "r"(a[2]), "r"(a[3]), "r"(b0), "r"(b1));
}
__device__ __forceinline__ void cp_async16(uint32_t dst, const void* src) {
    asm volatile("cp.async.cg.shared.global [%0], [%1], 16;\n" :: "r"(dst), "l"(src) : "memory");
}
#define CP_COMMIT() asm volatile("cp.async.commit_group;" ::: "memory")
#define CP_WAIT1()  asm volatile("cp.async.wait_group 1;" ::: "memory")

// fast tanh: tanh(t) = 1 - 2/(exp(2t)+1), rel err ~1e-6
__device__ __forceinline__ float fast_tanh3(float x, float sc3) {
    float t = x * sc3;
    float e;
    asm("ex2.approx.f32 %0, %1;" : "=f"(e) : "f"(t * 2.885390082f));
    float r;
    asm("rcp.approx.f32 %0, %1;" : "=f"(r) : "f"(e + 1.0f));
    return 3.0f * (1.0f - 2.0f * r);
}

// ---------------------------------------------------------------- K2: 4-CTA/SM HMMA GEMM
// 128 threads = 4 warps (2x2), warp tile 64x32, BM128 x BN64 x BK32, 3 stages
__global__ __launch_bounds__(128, 4) void gemm_kernel(const float* __restrict__ bias,
                                                      const float* __restrict__ scale,
                                                      float* __restrict__ out) {
    extern __shared__ __align__(16) char smem[];
    uint32_t sb;
    asm("{ .reg .u64 t; cvta.to.shared.u64 t, %1; cvt.u32.u64 %0, t; }" : "=r"(sb) : "l"(smem));

    int tid  = threadIdx.x;
    int wid  = tid >> 5;
    int lane = tid & 31;
    int wm   = wid >> 1;        // 0..1 (64 rows)
    int wn   = wid & 1;         // 0..1 (32 cols)
    int bm   = blockIdx.y;
    int bn   = blockIdx.x;

    float acc[4][4][4];
    #pragma unroll
    for (int i = 0; i < 4; i++)
        #pragma unroll
        for (int j = 0; j < 4; j++)
            #pragma unroll
            for (int k = 0; k < 4; k++) acc[i][j][k] = 0.f;

    int r8 = lane & 7;
    int q  = lane >> 3;

    // ldmatrix offsets (bytes within stage)
    uint32_t aoff[4], boff[2];
    #pragma unroll
    for (int mi = 0; mi < 4; mi++)
        aoff[mi] = (uint32_t)((wm * 64 + mi * 16 + r8 + (q & 1) * 8) * LDA + (q >> 1) * 8) * 2;
    #pragma unroll
    for (int ni = 0; ni < 2; ni++)
        boff[ni] = (uint32_t)(((q & 1) * 8 + r8) * LDB + wn * 32 + ni * 16 + (q >> 1) * 8) * 2 + A_STAGE_B;

    // cp.async offsets: A 4 chunks/thread (512 total), B 2 chunks/thread (256 total)
    uint32_t as_off[4], ag_off[4], bs_off[2], bg_off[2];
    #pragma unroll
    for (int i = 0; i < 4; i++) {
        int chunk = tid + i * 128;
        int arow = chunk >> 2, ac = chunk & 3;
        as_off[i] = (uint32_t)(arow * LDA + ac * 8) * 2;
        ag_off[i] = (uint32_t)arow * (D_Z * 2) + ac * 16;
    }
    #pragma unroll
    for (int i = 0; i < 2; i++) {
        int chunk = tid + i * 128;
        int brow = chunk >> 3, bc = chunk & 7;
        bs_off[i] = (uint32_t)(brow * LDB + bc * 8) * 2 + A_STAGE_B;
        bg_off[i] = (uint32_t)brow * (D_MODEL * 2) + bc * 16;
    }

    const char* Abase = (const char*)(g_zn + (size_t)(bm * BM) * D_Z);
    const char* Bbase = (const char*)(g_wb + (size_t)(bn * BN));

    // preload stages 0,1
    {
        #pragma unroll
        for (int i = 0; i < 4; i++) cp_async16(sb + as_off[i], Abase + ag_off[i]);
        #pragma unroll
        for (int i = 0; i < 2; i++) cp_async16(sb + bs_off[i], Bbase + bg_off[i]);
        CP_COMMIT();
        uint32_t s1 = sb + STAGE_B;
        const char* Ag = Abase + BK * 2;
        const char* Bg = Bbase + (size_t)BK * D_MODEL * 2;
        #pragma unroll
        for (int i = 0; i < 4; i++) cp_async16(s1 + as_off[i], Ag + ag_off[i]);
        #pragma unroll
        for (int i = 0; i < 2; i++) cp_async16(s1 + bs_off[i], Bg + bg_off[i]);
        CP_COMMIT();
    }

    const char* Agp = Abase + 2 * BK * 2;
    const char* Bgp = Bbase + (size_t)2 * BK * D_MODEL * 2;

    uint32_t abase = sb;
    const uint32_t send = sb + STAGES * STAGE_B;

    for (int kt = 0; kt < KITERS; kt++) {
        CP_WAIT1();
        __syncthreads();

        // refill stage kt+2
        if (kt + 2 < KITERS) {
            uint32_t p = abase + 2 * STAGE_B;
            uint32_t pbase = (p >= send) ? p - STAGES * STAGE_B : p;
            #pragma unroll
            for (int i = 0; i < 4; i++) cp_async16(pbase + as_off[i], Agp + ag_off[i]);
            #pragma unroll
            for (int i = 0; i < 2; i++) cp_async16(pbase + bs_off[i], Bgp + bg_off[i]);
            Agp += BK * 2;
            Bgp += (size_t)BK * D_MODEL * 2;
        }
        CP_COMMIT();

        #pragma unroll
        for (int ks = 0; ks < 2; ks++) {
            uint32_t ko2 = (uint32_t)(ks * 16) * 2;
            uint32_t kb  = (uint32_t)(ks * 16) * (LDB * 2);

            uint32_t af[4][4];
            #pragma unroll
            for (int mi = 0; mi < 4; mi++)
                ldmatrix_x4(af[mi], abase + aoff[mi] + ko2);

            uint32_t bf[8];
            ldmatrix_b(bf[0], bf[1], bf[2], bf[3], abase + boff[0] + kb);
            ldmatrix_b(bf[4], bf[5], bf[6], bf[7], abase + boff[1] + kb);

            #pragma unroll
            for (int mi = 0; mi < 4; mi++)
                #pragma unroll
                for (int nb = 0; nb < 4; nb++)
                    mma_16816(acc[mi][nb], af[mi], bf[nb * 2], bf[nb * 2 + 1]);
        }

        abase += STAGE_B;
        if (abase >= send) abase = sb;
    }

    // epilogue: out = 3*tanh((acc + bias)*scale/3)
    float sc3 = scale[0] * (1.0f / 3.0f);
    int rr = lane >> 2;
    int cq = (lane & 3) * 2;

    #pragma unroll
    for (int nb = 0; nb < 4; nb++) {
        int col = bn * BN + wn * 32 + nb * 8 + cq;
        float2 bv = *(const float2*)(bias + col);
        #pragma unroll
        for (int mi = 0; mi < 4; mi++) {
            int row = bm * BM + wm * 64 + mi * 16 + rr;
            float2 o0, o1;
            o0.x = fast_tanh3(acc[mi][nb][0] + bv.x, sc3);
            o0.y = fast_tanh3(acc[mi][nb][1] + bv.y, sc3);
            o1.x = fast_tanh3(acc[mi][nb][2] + bv.x, sc3);
            o1.y = fast_tanh3(acc[mi][nb][3] + bv.y, sc3);
            *(float2*)(out + (size_t)row * D_MODEL + col)       = o0;
            *(float2*)(out + (size_t)(row + 8) * D_MODEL + col) = o1;
        }
    }
}

// ---------------------------------------------------------------- launch
extern "C" void kernel_launch(void* const* d_in, const int* in_sizes, int n_in,
                              void* d_out, int out_size) {
    const float* z     = (const float*)d_in[0];
    const float* gamma = (const float*)d_in[1];
    const float* beta  = (const float*)d_in[2];
    const float* W     = (const float*)d_in[3];
    const float* b     = (const float*)d_in[4];
    const float* scale = (const float*)d_in[5];
    float* out = (float*)d_out;
    (void)in_sizes; (void)n_in; (void)out_size;

    cudaFuncSetAttribute(gemm_kernel, cudaFuncAttributeMaxDynamicSharedMemorySize, SMEM_TOTAL);

    prep_kernel<<<M_ROWS + WCONV_BLOCKS, 256>>>(z, gamma, beta, W);
    dim3 grid(D_MODEL / BN, M_ROWS / BM);   // (64, 128) = 8192 CTAs, 4/SM
    gemm_kernel<<<grid, 128, SMEM_TOTAL>>>(b, scale, out);
}

// round 10
// speedup vs baseline: 1.0918x; 1.0918x over previous
#include <cuda_runtime.h>
#include <cuda_fp16.h>
#include <cstdint>

// ---------------------------------------------------------------- constants
#define D_Z     1024
#define D_MODEL 4096
#define M_ROWS  16384
#define EPS     1e-5f

#define BM 128
#define BN 128
#define BK 64
#define KITERS (D_Z / BK)      // 16
#define STAGES 3

#define LDA 72                  // 64 + 8 pad (fp16): conflict-free ldmatrix
#define LDB 136                 // 128 + 8 pad
#define A_STAGE_B (BM * LDA * 2)          // 18432 B
#define B_STAGE_B (BK * LDB * 2)          // 17408 B
#define STAGE_B   (A_STAGE_B + B_STAGE_B) // 35840 B
#define SMEM_TOTAL (STAGES * STAGE_B)     // 107520 B -> 2 CTAs/SM

#define WCONV_BLOCKS 1024

// scratch (allocation-free rule: device globals)
__device__ __half g_zn[(size_t)M_ROWS * D_Z];     // LN output fp16 [M,K]
__device__ __half g_wb[(size_t)D_Z * D_MODEL];    // W fp16 [K,N]

// ---------------------------------------------------------------- K1: merged prep
__global__ __launch_bounds__(256) void prep_kernel(const float* __restrict__ z,
                                                   const float* __restrict__ gamma,
                                                   const float* __restrict__ beta,
                                                   const float* __restrict__ W) {
    int blk = blockIdx.x;
    int t   = threadIdx.x;

    if (blk >= M_ROWS) {
        size_t base = (size_t)(blk - M_ROWS) * 1024 + t;
        __half2* dst = (__half2*)g_wb;
        #pragma unroll
        for (int u = 0; u < 4; u++) {
            size_t i = base + (size_t)u * 256;
            float4 v = ((const float4*)W)[i];
            dst[i * 2 + 0] = __floats2half2_rn(v.x, v.y);
            dst[i * 2 + 1] = __floats2half2_rn(v.z, v.w);
        }
        return;
    }

    int row = blk, lane = t & 31, wid = t >> 5;
    const float4* zp = (const float4*)(z + (size_t)row * D_Z);
    float4 v = zp[t];

    float s  = v.x + v.y + v.z + v.w;
    float ss = v.x * v.x + v.y * v.y + v.z * v.z + v.w * v.w;
    #pragma unroll
    for (int o = 16; o > 0; o >>= 1) {
        s  += __shfl_xor_sync(0xffffffffu, s, o);
        ss += __shfl_xor_sync(0xffffffffu, ss, o);
    }
    __shared__ float sbuf[8], ssbuf[8], smu, srstd;
    if (lane == 0) { sbuf[wid] = s; ssbuf[wid] = ss; }
    __syncthreads();
    if (t == 0) {
        float S = 0.f, SS = 0.f;
        #pragma unroll
        for (int i = 0; i < 8; i++) { S += sbuf[i]; SS += ssbuf[i]; }
        float mu  = S * (1.0f / D_Z);
        float var = SS * (1.0f / D_Z) - mu * mu;
        smu = mu; srstd = rsqrtf(var + EPS);
    }
    __syncthreads();
    float mu = smu, rstd = srstd;

    float4 g = ((const float4*)gamma)[t];
    float4 b = ((const float4*)beta)[t];
    float o0 = (v.x - mu) * rstd * g.x + b.x;
    float o1 = (v.y - mu) * rstd * g.y + b.y;
    float o2 = (v.z - mu) * rstd * g.z + b.z;
    float o3 = (v.w - mu) * rstd * g.w + b.w;

    __half2* dst = (__half2*)(g_zn + (size_t)row * D_Z);
    dst[t * 2 + 0] = __floats2half2_rn(o0, o1);
    dst[t * 2 + 1] = __floats2half2_rn(o2, o3);
}

// ---------------------------------------------------------------- PTX wrappers
__device__ __forceinline__ void ldmatrix_x4(uint32_t r[4], uint32_t addr) {
    asm volatile("ldmatrix.sync.aligned.m8n8.x4.shared.b16 {%0,%1,%2,%3}, [%4];\n"
                 : "=r"(r[0]), "=r"(r[1]), "=r"(r[2]), "=r"(r[3]) : "r"(addr));
}
__device__ __forceinline__ void ldmatrix_b(uint32_t& b00, uint32_t& b01,
                                           uint32_t& b10, uint32_t& b11, uint32_t addr) {
    asm volatile("ldmatrix.sync.aligned.m8n8.x4.trans.shared.b16 {%0,%1,%2,%3}, [%4];\n"
                 : "=r"(b00), "=r"(b01), "=r"(b10), "=r"(b11) : "r"(addr));
}
__device__ __forceinline__ void mma_16816(float c[4], const uint32_t a[4],
                                          uint32_t b0, uint32_t b1) {
    asm volatile("mma.sync.aligned.m16n8k16.row.col.f32.f16.f16.f32 "
                 "{%0,%1,%2,%3}, {%4,%5,%6,%7}, {%8,%9}, {%0,%1,%2,%3};\n"
                 : "+f"(c[0]), "+f"(c[1]), "+f"(c[2]), "+f"(c[3])
                 : "r"(a[0]), "r"(a[1]), "r"(a[2]), "r"(a[3]), "r"(b0), "r"(b1));
}
__device__ __forceinline__ void cp_async16(uint32_t dst, const void* src) {
    asm volatile("cp.async.cg.shared.global [%0], [%1], 16;\n" :: "r"(dst), "l"(src) : "memory");
}
#define CP_COMMIT() asm volatile("cp.async.commit_group;" ::: "memory")
#define CP_WAIT1()  asm volatile("cp.async.wait_group 1;" ::: "memory")

// fast tanh: tanh(t) = 1 - 2/(exp(2t)+1), rel err ~1e-6
__device__ __forceinline__ float fast_tanh3(float x, float sc3) {
    float t = x * sc3;
    float e;
    asm("ex2.approx.f32 %0, %1;" : "=f"(e) : "f"(t * 2.885390082f));
    float r;
    asm("rcp.approx.f32 %0, %1;" : "=f"(r) : "f"(e + 1.0f));
    return 3.0f * (1.0f - 2.0f * r);
}

// ---------------------------------------------------------------- K2: GEMM
// 128 threads = 4 warps (2x2), warp tile 64x64, BM128 x BN128 x BK64,
// 3 stages, 2 CTAs/SM, up to 255 regs/thread.
__global__ __launch_bounds__(128, 2) void gemm_kernel(const float* __restrict__ bias,
                                                      const float* __restrict__ scale,
                                                      float* __restrict__ out) {
    extern __shared__ __align__(16) char smem[];
    uint32_t sb;
    asm("{ .reg .u64 t; cvta.to.shared.u64 t, %1; cvt.u32.u64 %0, t; }" : "=r"(sb) : "l"(smem));

    int tid  = threadIdx.x;
    int wid  = tid >> 5;
    int lane = tid & 31;
    int wm   = wid >> 1;        // 0..1 (64 rows)
    int wn   = wid & 1;         // 0..1 (64 cols)
    int bm   = blockIdx.y;
    int bn   = blockIdx.x;

    float acc[4][8][4];
    #pragma unroll
    for (int i = 0; i < 4; i++)
        #pragma unroll
        for (int j = 0; j < 8; j++)
            #pragma unroll
            for (int k = 0; k < 4; k++) acc[i][j][k] = 0.f;

    int r8 = lane & 7;
    int q  = lane >> 3;

    // ldmatrix offsets (bytes within stage)
    uint32_t aoff[4], boff[4];
    #pragma unroll
    for (int mi = 0; mi < 4; mi++)
        aoff[mi] = (uint32_t)((wm * 64 + mi * 16 + r8 + (q & 1) * 8) * LDA + (q >> 1) * 8) * 2;
    #pragma unroll
    for (int ni = 0; ni < 4; ni++)
        boff[ni] = (uint32_t)(((q & 1) * 8 + r8) * LDB + wn * 64 + ni * 16 + (q >> 1) * 8) * 2 + A_STAGE_B;

    // cp.async offsets: A 1024 chunks -> 8/thread; B 1024 chunks -> 8/thread
    uint32_t as_off[8], ag_off[8], bs_off[8], bg_off[8];
    #pragma unroll
    for (int i = 0; i < 8; i++) {
        int chunk = tid + i * 128;
        int arow = chunk >> 3, ac = chunk & 7;
        as_off[i] = (uint32_t)(arow * LDA + ac * 8) * 2;
        ag_off[i] = (uint32_t)arow * (D_Z * 2) + ac * 16;
        int brow = chunk >> 4, bc = chunk & 15;
        bs_off[i] = (uint32_t)(brow * LDB + bc * 8) * 2 + A_STAGE_B;
        bg_off[i] = (uint32_t)brow * (D_MODEL * 2) + bc * 16;
    }

    const char* Abase = (const char*)(g_zn + (size_t)(bm * BM) * D_Z);
    const char* Bbase = (const char*)(g_wb + (size_t)(bn * BN));

    // preload stages 0,1
    {
        #pragma unroll
        for (int i = 0; i < 8; i++) cp_async16(sb + as_off[i], Abase + ag_off[i]);
        #pragma unroll
        for (int i = 0; i < 8; i++) cp_async16(sb + bs_off[i], Bbase + bg_off[i]);
        CP_COMMIT();
        uint32_t s1 = sb + STAGE_B;
        const char* Ag = Abase + BK * 2;
        const char* Bg = Bbase + (size_t)BK * D_MODEL * 2;
        #pragma unroll
        for (int i = 0; i < 8; i++) cp_async16(s1 + as_off[i], Ag + ag_off[i]);
        #pragma unroll
        for (int i = 0; i < 8; i++) cp_async16(s1 + bs_off[i], Bg + bg_off[i]);
        CP_COMMIT();
    }

    const char* Agp = Abase + 2 * BK * 2;
    const char* Bgp = Bbase + (size_t)2 * BK * D_MODEL * 2;

    uint32_t abase = sb;
    const uint32_t send = sb + STAGES * STAGE_B;

    uint32_t af[2][4][4];       // [buf][mi][frag]
    uint32_t bf[2][16];         // [buf][ni*4 .. ] (4 tiles x (lo,hi))

    for (int kt = 0; kt < KITERS; kt++) {
        CP_WAIT1();
        __syncthreads();

        // fragments for ks=0 into buf0
        #pragma unroll
        for (int mi = 0; mi < 4; mi++) ldmatrix_x4(af[0][mi], abase + aoff[mi]);
        #pragma unroll
        for (int ni = 0; ni < 4; ni++)
            ldmatrix_b(bf[0][ni * 4 + 0], bf[0][ni * 4 + 1],
                       bf[0][ni * 4 + 2], bf[0][ni * 4 + 3], abase + boff[ni]);

        // refill stage kt+2
        if (kt + 2 < KITERS) {
            uint32_t p = abase + 2 * STAGE_B;
            uint32_t pbase = (p >= send) ? p - STAGES * STAGE_B : p;
            #pragma unroll
            for (int i = 0; i < 8; i++) cp_async16(pbase + as_off[i], Agp + ag_off[i]);
            #pragma unroll
            for (int i = 0; i < 8; i++) cp_async16(pbase + bs_off[i], Bgp + bg_off[i]);
            Agp += BK * 2;
            Bgp += (size_t)BK * D_MODEL * 2;
        }
        CP_COMMIT();

        #pragma unroll
        for (int ks = 0; ks < 4; ks++) {
            int cur = ks & 1;
            // prefetch fragments for ks+1 into the other buffer
            if (ks < 3) {
                uint32_t ko2 = (uint32_t)((ks + 1) * 16) * 2;
                uint32_t kb1 = (uint32_t)((ks + 1) * 16) * (LDB * 2);
                #pragma unroll
                for (int mi = 0; mi < 4; mi++)
                    ldmatrix_x4(af[cur ^ 1][mi], abase + aoff[mi] + ko2);
                #pragma unroll
                for (int ni = 0; ni < 4; ni++)
                    ldmatrix_b(bf[cur ^ 1][ni * 4 + 0], bf[cur ^ 1][ni * 4 + 1],
                               bf[cur ^ 1][ni * 4 + 2], bf[cur ^ 1][ni * 4 + 3],
                               abase + boff[ni] + kb1);
            }
            // 32 MMAs on current buffer
            #pragma unroll
            for (int mi = 0; mi < 4; mi++)
                #pragma unroll
                for (int nb = 0; nb < 8; nb++)
                    mma_16816(acc[mi][nb], af[cur][mi],
                              bf[cur][(nb >> 1) * 4 + (nb & 1) * 2],
                              bf[cur][(nb >> 1) * 4 + (nb & 1) * 2 + 1]);
        }

        abase += STAGE_B;
        if (abase >= send) abase = sb;
    }

    // epilogue: out = 3*tanh((acc + bias)*scale/3)
    float sc3 = scale[0] * (1.0f / 3.0f);
    int rr = lane >> 2;
    int cq = (lane & 3) * 2;

    #pragma unroll
    for (int nb = 0; nb < 8; nb++) {
        int col = bn * BN + wn * 64 + nb * 8 + cq;
        float2 bv = *(const float2*)(bias + col);
        #pragma unroll
        for (int mi = 0; mi < 4; mi++) {
            int row = bm * BM + wm * 64 + mi * 16 + rr;
            float2 o0, o1;
            o0.x = fast_tanh3(acc[mi][nb][0] + bv.x, sc3);
            o0.y = fast_tanh3(acc[mi][nb][1] + bv.y, sc3);
            o1.x = fast_tanh3(acc[mi][nb][2] + bv.x, sc3);
            o1.y = fast_tanh3(acc[mi][nb][3] + bv.y, sc3);
            *(float2*)(out + (size_t)row * D_MODEL + col)       = o0;
            *(float2*)(out + (size_t)(row + 8) * D_MODEL + col) = o1;
        }
    }
}

// ---------------------------------------------------------------- launch
extern "C" void kernel_launch(void* const* d_in, const int* in_sizes, int n_in,
                              void* d_out, int out_size) {
    const float* z     = (const float*)d_in[0];
    const float* gamma = (const float*)d_in[1];
    const float* beta  = (const float*)d_in[2];
    const float* W     = (const float*)d_in[3];
    const float* b     = (const float*)d_in[4];
    const float* scale = (const float*)d_in[5];
    float* out = (float*)d_out;
    (void)in_sizes; (void)n_in; (void)out_size;

    cudaFuncSetAttribute(gemm_kernel, cudaFuncAttributeMaxDynamicSharedMemorySize, SMEM_TOTAL);

    prep_kernel<<<M_ROWS + WCONV_BLOCKS, 256>>>(z, gamma, beta, W);
    dim3 grid(D_MODEL / BN, M_ROWS / BM);   // (32, 128) = 4096 CTAs, 2/SM
    gemm_kernel<<<grid, 128, SMEM_TOTAL>>>(b, scale, out);
}

// round 11
// speedup vs baseline: 1.1743x; 1.0755x over previous
#include <cuda_runtime.h>
#include <cuda_fp16.h>
#include <cstdint>

// ---------------------------------------------------------------- constants
#define D_Z     1024
#define D_MODEL 4096
#define M_ROWS  16384
#define EPS     1e-5f

#define BM 128
#define BN 128
#define BK 64
#define KITERS (D_Z / BK)      // 16
#define STAGES 3

#define LDA 72                  // 64 + 8 pad (fp16): conflict-free ldmatrix
#define LDB 136                 // 128 + 8 pad
#define A_STAGE_B (BM * LDA * 2)          // 18432 B
#define B_STAGE_B (BK * LDB * 2)          // 17408 B
#define STAGE_B   (A_STAGE_B + B_STAGE_B) // 35840 B
#define SMEM_TOTAL (STAGES * STAGE_B)     // 107520 B -> 2 CTAs/SM

#define LN_BLOCKS   (M_ROWS / 8)          // 2048 (8 rows per block)
#define WCONV_BLOCKS 1024

// scratch (allocation-free rule: device globals)
__device__ __half g_zn[(size_t)M_ROWS * D_Z];     // LN output fp16 [M,K]
__device__ __half g_wb[(size_t)D_Z * D_MODEL];    // W fp16 [K,N]

// ---------------------------------------------------------------- K1: merged prep
// blocks [0, LN_BLOCKS): warp-per-row LayerNorm (8 rows/block, no barriers)
// blocks [LN_BLOCKS, +WCONV_BLOCKS): W fp32 -> fp16
__global__ __launch_bounds__(256) void prep_kernel(const float* __restrict__ z,
                                                   const float* __restrict__ gamma,
                                                   const float* __restrict__ beta,
                                                   const float* __restrict__ W) {
    int blk = blockIdx.x;
    int t   = threadIdx.x;

    if (blk >= LN_BLOCKS) {
        size_t base = (size_t)(blk - LN_BLOCKS) * 1024 + t;
        __half2* dst = (__half2*)g_wb;
        #pragma unroll
        for (int u = 0; u < 4; u++) {
            size_t i = base + (size_t)u * 256;
            float4 v = ((const float4*)W)[i];
            dst[i * 2 + 0] = __floats2half2_rn(v.x, v.y);
            dst[i * 2 + 1] = __floats2half2_rn(v.z, v.w);
        }
        return;
    }

    // ---- warp-per-row LayerNorm
    int wid  = t >> 5;
    int lane = t & 31;
    int row  = blk * 8 + wid;

    const float4* zp = (const float4*)(z + (size_t)row * D_Z);
    float4 v[8];
    #pragma unroll
    for (int c = 0; c < 8; c++) v[c] = zp[lane + c * 32];

    float s = 0.f, ss = 0.f;
    #pragma unroll
    for (int c = 0; c < 8; c++) {
        s  += v[c].x + v[c].y + v[c].z + v[c].w;
        ss += v[c].x * v[c].x + v[c].y * v[c].y + v[c].z * v[c].z + v[c].w * v[c].w;
    }
    #pragma unroll
    for (int o = 16; o > 0; o >>= 1) {
        s  += __shfl_xor_sync(0xffffffffu, s, o);
        ss += __shfl_xor_sync(0xffffffffu, ss, o);
    }
    float mu   = s * (1.0f / D_Z);
    float var  = ss * (1.0f / D_Z) - mu * mu;
    float rstd = rsqrtf(var + EPS);

    const float4* gp = (const float4*)gamma;
    const float4* bp = (const float4*)beta;
    __half2* dst = (__half2*)(g_zn + (size_t)row * D_Z);
    #pragma unroll
    for (int c = 0; c < 8; c++) {
        float4 g = gp[lane + c * 32];
        float4 b = bp[lane + c * 32];
        float o0 = (v[c].x - mu) * rstd * g.x + b.x;
        float o1 = (v[c].y - mu) * rstd * g.y + b.y;
        float o2 = (v[c].z - mu) * rstd * g.z + b.z;
        float o3 = (v[c].w - mu) * rstd * g.w + b.w;
        dst[(lane + c * 32) * 2 + 0] = __floats2half2_rn(o0, o1);
        dst[(lane + c * 32) * 2 + 1] = __floats2half2_rn(o2, o3);
    }
}

// ---------------------------------------------------------------- PTX wrappers
__device__ __forceinline__ void ldmatrix_x4(uint32_t r[4], uint32_t addr) {
    asm volatile("ldmatrix.sync.aligned.m8n8.x4.shared.b16 {%0,%1,%2,%3}, [%4];\n"
                 : "=r"(r[0]), "=r"(r[1]), "=r"(r[2]), "=r"(r[3]) : "r"(addr));
}
__device__ __forceinline__ void ldmatrix_b(uint32_t& b00, uint32_t& b01,
                                           uint32_t& b10, uint32_t& b11, uint32_t addr) {
    asm volatile("ldmatrix.sync.aligned.m8n8.x4.trans.shared.b16 {%0,%1,%2,%3}, [%4];\n"
                 : "=r"(b00), "=r"(b01), "=r"(b10), "=r"(b11) : "r"(addr));
}
__device__ __forceinline__ void mma_16816(float c[4], const uint32_t a[4],
                                          uint32_t b0, uint32_t b1) {
    asm volatile("mma.sync.aligned.m16n8k16.row.col.f32.f16.f16.f32 "
                 "{%0,%1,%2,%3}, {%4,%5,%6,%7}, {%8,%9}, {%0,%1,%2,%3};\n"
                 : "+f"(c[0]), "+f"(c[1]), "+f"(c[2]), "+f"(c[3])
                 : "r"(a[0]), "r"(a[1]), "r"(a[2]), "r"(a[3]), "r"(b0), "r"(b1));
}
__device__ __forceinline__ void cp_async16(uint32_t dst, const void* src) {
    asm volatile("cp.async.cg.shared.global [%0], [%1], 16;\n" :: "r"(dst), "l"(src) : "memory");
}
#define CP_COMMIT() asm volatile("cp.async.commit_group;" ::: "memory")
#define CP_WAIT1()  asm volatile("cp.async.wait_group 1;" ::: "memory")

// fast tanh: tanh(t) = 1 - 2/(exp(2t)+1), rel err ~1e-6
__device__ __forceinline__ float fast_tanh3(float x, float sc3) {
    float t = x * sc3;
    float e;
    asm("ex2.approx.f32 %0, %1;" : "=f"(e) : "f"(t * 2.885390082f));
    float r;
    asm("rcp.approx.f32 %0, %1;" : "=f"(r) : "f"(e + 1.0f));
    return 3.0f * (1.0f - 2.0f * r);
}

// ---------------------------------------------------------------- K2: GEMM
// 128 threads = 4 warps (2x2), warp tile 64x64, BM128 x BN128 x BK64,
// 3 stages, 2 CTAs/SM. Stage boundary (wait+bar) hidden under last ks MMA group.
__device__ __forceinline__ void load_frags(uint32_t base, uint32_t af[4][4], uint32_t bf[16],
                                           const uint32_t aoff[4], const uint32_t boff[4],
                                           uint32_t ko2, uint32_t kb) {
    #pragma unroll
    for (int mi = 0; mi < 4; mi++) ldmatrix_x4(af[mi], base + aoff[mi] + ko2);
    #pragma unroll
    for (int ni = 0; ni < 4; ni++)
        ldmatrix_b(bf[ni * 4 + 0], bf[ni * 4 + 1], bf[ni * 4 + 2], bf[ni * 4 + 3],
                   base + boff[ni] + kb);
}

__global__ __launch_bounds__(128, 2) void gemm_kernel(const float* __restrict__ bias,
                                                      const float* __restrict__ scale,
                                                      float* __restrict__ out) {
    extern __shared__ __align__(16) char smem[];
    uint32_t sb;
    asm("{ .reg .u64 t; cvta.to.shared.u64 t, %1; cvt.u32.u64 %0, t; }" : "=r"(sb) : "l"(smem));

    int tid  = threadIdx.x;
    int wid  = tid >> 5;
    int lane = tid & 31;
    int wm   = wid >> 1;        // 0..1 (64 rows)
    int wn   = wid & 1;         // 0..1 (64 cols)
    int bm   = blockIdx.y;
    int bn   = blockIdx.x;

    float acc[4][8][4];
    #pragma unroll
    for (int i = 0; i < 4; i++)
        #pragma unroll
        for (int j = 0; j < 8; j++)
            #pragma unroll
            for (int k = 0; k < 4; k++) acc[i][j][k] = 0.f;

    int r8 = lane & 7;
    int q  = lane >> 3;

    uint32_t aoff[4], boff[4];
    #pragma unroll
    for (int mi = 0; mi < 4; mi++)
        aoff[mi] = (uint32_t)((wm * 64 + mi * 16 + r8 + (q & 1) * 8) * LDA + (q >> 1) * 8) * 2;
    #pragma unroll
    for (int ni = 0; ni < 4; ni++)
        boff[ni] = (uint32_t)(((q & 1) * 8 + r8) * LDB + wn * 64 + ni * 16 + (q >> 1) * 8) * 2 + A_STAGE_B;

    uint32_t as_off[8], ag_off[8], bs_off[8], bg_off[8];
    #pragma unroll
    for (int i = 0; i < 8; i++) {
        int chunk = tid + i * 128;
        int arow = chunk >> 3, ac = chunk & 7;
        as_off[i] = (uint32_t)(arow * LDA + ac * 8) * 2;
        ag_off[i] = (uint32_t)arow * (D_Z * 2) + ac * 16;
        int brow = chunk >> 4, bc = chunk & 15;
        bs_off[i] = (uint32_t)(brow * LDB + bc * 8) * 2 + A_STAGE_B;
        bg_off[i] = (uint32_t)brow * (D_MODEL * 2) + bc * 16;
    }

    const char* Abase = (const char*)(g_zn + (size_t)(bm * BM) * D_Z);
    const char* Bbase = (const char*)(g_wb + (size_t)(bn * BN));

    // preload stages 0,1
    {
        #pragma unroll
        for (int i = 0; i < 8; i++) cp_async16(sb + as_off[i], Abase + ag_off[i]);
        #pragma unroll
        for (int i = 0; i < 8; i++) cp_async16(sb + bs_off[i], Bbase + bg_off[i]);
        CP_COMMIT();
        uint32_t s1 = sb + STAGE_B;
        const char* Ag = Abase + BK * 2;
        const char* Bg = Bbase + (size_t)BK * D_MODEL * 2;
        #pragma unroll
        for (int i = 0; i < 8; i++) cp_async16(s1 + as_off[i], Ag + ag_off[i]);
        #pragma unroll
        for (int i = 0; i < 8; i++) cp_async16(s1 + bs_off[i], Bg + bg_off[i]);
        CP_COMMIT();
    }

    const char* Agp = Abase + 2 * BK * 2;
    const char* Bgp = Bbase + (size_t)2 * BK * D_MODEL * 2;

    uint32_t abase = sb;
    const uint32_t send = sb + STAGES * STAGE_B;

    uint32_t af[2][4][4];
    uint32_t bf[2][16];

    // stage 0 ready -> load ks=0 fragments into buf 0
    CP_WAIT1();
    __syncthreads();
    load_frags(abase, af[0], bf[0], aoff, boff, 0, 0);

    for (int kt = 0; kt < KITERS; kt++) {
        // refill stage kt+2 (fragments for ks=0 already in regs -> overlaps MMA)
        if (kt + 2 < KITERS) {
            uint32_t p = abase + 2 * STAGE_B;
            uint32_t pbase = (p >= send) ? p - STAGES * STAGE_B : p;
            #pragma unroll
            for (int i = 0; i < 8; i++) cp_async16(pbase + as_off[i], Agp + ag_off[i]);
            #pragma unroll
            for (int i = 0; i < 8; i++) cp_async16(pbase + bs_off[i], Bgp + bg_off[i]);
            Agp += BK * 2;
            Bgp += (size_t)BK * D_MODEL * 2;
        }
        CP_COMMIT();

        uint32_t nbase = abase + STAGE_B;
        if (nbase >= send) nbase = sb;

        #pragma unroll
        for (int ks = 0; ks < 4; ks++) {
            int cur = ks & 1;
            if (ks < 3) {
                // prefetch next ks fragments of this stage
                load_frags(abase, af[cur ^ 1], bf[cur ^ 1], aoff, boff,
                           (uint32_t)((ks + 1) * 16) * 2,
                           (uint32_t)((ks + 1) * 16) * (LDB * 2));
            } else if (kt + 1 < KITERS) {
                // stage boundary hidden under the last MMA group:
                // ensure stage kt+1 resident, then load its ks=0 fragments
                CP_WAIT1();
                __syncthreads();
                load_frags(nbase, af[cur ^ 1], bf[cur ^ 1], aoff, boff, 0, 0);
            }
            #pragma unroll
            for (int mi = 0; mi < 4; mi++)
                #pragma unroll
                for (int nb = 0; nb < 8; nb++)
                    mma_16816(acc[mi][nb], af[cur][mi],
                              bf[cur][(nb >> 1) * 4 + (nb & 1) * 2],
                              bf[cur][(nb >> 1) * 4 + (nb & 1) * 2 + 1]);
        }

        abase = nbase;
    }

    // epilogue: out = 3*tanh((acc + bias)*scale/3)
    float sc3 = scale[0] * (1.0f / 3.0f);
    int rr = lane >> 2;
    int cq = (lane & 3) * 2;

    #pragma unroll
    for (int nb = 0; nb < 8; nb++) {
        int col = bn * BN + wn * 64 + nb * 8 + cq;
        float2 bv = *(const float2*)(bias + col);
        #pragma unroll
        for (int mi = 0; mi < 4; mi++) {
            int row = bm * BM + wm * 64 + mi * 16 + rr;
            float2 o0, o1;
            o0.x = fast_tanh3(acc[mi][nb][0] + bv.x, sc3);
            o0.y = fast_tanh3(acc[mi][nb][1] + bv.y, sc3);
            o1.x = fast_tanh3(acc[mi][nb][2] + bv.x, sc3);
            o1.y = fast_tanh3(acc[mi][nb][3] + bv.y, sc3);
            *(float2*)(out + (size_t)row * D_MODEL + col)       = o0;
            *(float2*)(out + (size_t)(row + 8) * D_MODEL + col) = o1;
        }
    }
}

// ---------------------------------------------------------------- launch
extern "C" void kernel_launch(void* const* d_in, const int* in_sizes, int n_in,
                              void* d_out, int out_size) {
    const float* z     = (const float*)d_in[0];
    const float* gamma = (const float*)d_in[1];
    const float* beta  = (const float*)d_in[2];
    const float* W     = (const float*)d_in[3];
    const float* b     = (const float*)d_in[4];
    const float* scale = (const float*)d_in[5];
    float* out = (float*)d_out;
    (void)in_sizes; (void)n_in; (void)out_size;

    cudaFuncSetAttribute(gemm_kernel, cudaFuncAttributeMaxDynamicSharedMemorySize, SMEM_TOTAL);

    prep_kernel<<<LN_BLOCKS + WCONV_BLOCKS, 256>>>(z, gamma, beta, W);
    dim3 grid(D_MODEL / BN, M_ROWS / BM);   // (32, 128) = 4096 CTAs, 2/SM
    gemm_kernel<<<grid, 128, SMEM_TOTAL>>>(b, scale, out);
}

// round 12
// speedup vs baseline: 1.2753x; 1.0860x over previous
#include <cuda_runtime.h>
#include <cuda_fp16.h>
#include <cstdint>

// ---------------------------------------------------------------- constants
#define D_Z     1024
#define D_MODEL 4096
#define M_ROWS  16384
#define EPS     1e-5f

#define BM 128
#define BN 128
#define BK 64
#define KITERS (D_Z / BK)      // 16
#define STAGES 3

#define LDA 72                  // 64 + 8 pad (fp16): conflict-free ldmatrix
#define LDB 136                 // 128 + 8 pad
#define A_STAGE_B (BM * LDA * 2)          // 18432 B
#define B_STAGE_B (BK * LDB * 2)          // 17408 B
#define STAGE_B   (A_STAGE_B + B_STAGE_B) // 35840 B
#define SMEM_TOTAL (STAGES * STAGE_B)     // 107520 B -> 2 CTAs/SM

#define LN_BLOCKS   (M_ROWS / 8)          // 2048 (8 rows per block)
#define WCONV_BLOCKS 1024

// scratch (allocation-free rule: device globals)
__device__ __half g_zn[(size_t)M_ROWS * D_Z];     // LN output fp16 [M,K]
__device__ __half g_wb[(size_t)D_Z * D_MODEL];    // W fp16 [K,N]

// ---------------------------------------------------------------- K1: merged prep
__global__ __launch_bounds__(256) void prep_kernel(const float* __restrict__ z,
                                                   const float* __restrict__ gamma,
                                                   const float* __restrict__ beta,
                                                   const float* __restrict__ W) {
    int blk = blockIdx.x;
    int t   = threadIdx.x;

    if (blk >= LN_BLOCKS) {
        size_t base = (size_t)(blk - LN_BLOCKS) * 1024 + t;
        __half2* dst = (__half2*)g_wb;
        #pragma unroll
        for (int u = 0; u < 4; u++) {
            size_t i = base + (size_t)u * 256;
            float4 v = ((const float4*)W)[i];
            dst[i * 2 + 0] = __floats2half2_rn(v.x, v.y);
            dst[i * 2 + 1] = __floats2half2_rn(v.z, v.w);
        }
        return;
    }

    // ---- warp-per-row LayerNorm (no block barriers)
    int wid  = t >> 5;
    int lane = t & 31;
    int row  = blk * 8 + wid;

    const float4* zp = (const float4*)(z + (size_t)row * D_Z);
    float4 v[8];
    #pragma unroll
    for (int c = 0; c < 8; c++) v[c] = zp[lane + c * 32];

    float s = 0.f, ss = 0.f;
    #pragma unroll
    for (int c = 0; c < 8; c++) {
        s  += v[c].x + v[c].y + v[c].z + v[c].w;
        ss += v[c].x * v[c].x + v[c].y * v[c].y + v[c].z * v[c].z + v[c].w * v[c].w;
    }
    #pragma unroll
    for (int o = 16; o > 0; o >>= 1) {
        s  += __shfl_xor_sync(0xffffffffu, s, o);
        ss += __shfl_xor_sync(0xffffffffu, ss, o);
    }
    float mu   = s * (1.0f / D_Z);
    float var  = ss * (1.0f / D_Z) - mu * mu;
    float rstd = rsqrtf(var + EPS);

    const float4* gp = (const float4*)gamma;
    const float4* bp = (const float4*)beta;
    uint2* dst = (uint2*)(g_zn + (size_t)row * D_Z);
    #pragma unroll
    for (int c = 0; c < 8; c++) {
        float4 g = gp[lane + c * 32];
        float4 b = bp[lane + c * 32];
        float o0 = (v[c].x - mu) * rstd * g.x + b.x;
        float o1 = (v[c].y - mu) * rstd * g.y + b.y;
        float o2 = (v[c].z - mu) * rstd * g.z + b.z;
        float o3 = (v[c].w - mu) * rstd * g.w + b.w;
        __half2 h0 = __floats2half2_rn(o0, o1);
        __half2 h1 = __floats2half2_rn(o2, o3);
        uint2 pack;
        pack.x = *(uint32_t*)&h0;
        pack.y = *(uint32_t*)&h1;
        dst[lane + c * 32] = pack;
    }
}

// ---------------------------------------------------------------- PTX wrappers
__device__ __forceinline__ void ldmatrix_x4(uint32_t r[4], uint32_t addr) {
    asm volatile("ldmatrix.sync.aligned.m8n8.x4.shared.b16 {%0,%1,%2,%3}, [%4];\n"
                 : "=r"(r[0]), "=r"(r[1]), "=r"(r[2]), "=r"(r[3]) : "r"(addr));
}
__device__ __forceinline__ void ldmatrix_b(uint32_t& b00, uint32_t& b01,
                                           uint32_t& b10, uint32_t& b11, uint32_t addr) {
    asm volatile("ldmatrix.sync.aligned.m8n8.x4.trans.shared.b16 {%0,%1,%2,%3}, [%4];\n"
                 : "=r"(b00), "=r"(b01), "=r"(b10), "=r"(b11) : "r"(addr));
}
__device__ __forceinline__ void mma_16816(float c[4], const uint32_t a[4],
                                          uint32_t b0, uint32_t b1) {
    asm volatile("mma.sync.aligned.m16n8k16.row.col.f32.f16.f16.f32 "
                 "{%0,%1,%2,%3}, {%4,%5,%6,%7}, {%8,%9}, {%0,%1,%2,%3};\n"
                 : "+f"(c[0]), "+f"(c[1]), "+f"(c[2]), "+f"(c[3])
                 : "r"(a[0]), "r"(a[1]), "r"(a[2]), "r"(a[3]), "r"(b0), "r"(b1));
}
__device__ __forceinline__ void cp_async16(uint32_t dst, const void* src) {
    asm volatile("cp.async.cg.shared.global [%0], [%1], 16;\n" :: "r"(dst), "l"(src) : "memory");
}
#define CP_COMMIT() asm volatile("cp.async.commit_group;" ::: "memory")
#define CP_WAIT1()  asm volatile("cp.async.wait_group 1;" ::: "memory")

// fast tanh: tanh(t) = 1 - 2/(exp(2t)+1), rel err ~1e-6
__device__ __forceinline__ float fast_tanh3(float x, float sc3) {
    float t = x * sc3;
    float e;
    asm("ex2.approx.f32 %0, %1;" : "=f"(e) : "f"(t * 2.885390082f));
    float r;
    asm("rcp.approx.f32 %0, %1;" : "=f"(r) : "f"(e + 1.0f));
    return 3.0f * (1.0f - 2.0f * r);
}

// ---------------------------------------------------------------- K2: GEMM
__device__ __forceinline__ void load_frags(uint32_t base, uint32_t af[4][4], uint32_t bf[16],
                                           const uint32_t aoff[4], const uint32_t boff[4],
                                           uint32_t ko2, uint32_t kb) {
    #pragma unroll
    for (int mi = 0; mi < 4; mi++) ldmatrix_x4(af[mi], base + aoff[mi] + ko2);
    #pragma unroll
    for (int ni = 0; ni < 4; ni++)
        ldmatrix_b(bf[ni * 4 + 0], bf[ni * 4 + 1], bf[ni * 4 + 2], bf[ni * 4 + 3],
                   base + boff[ni] + kb);
}

__global__ __launch_bounds__(128, 2) void gemm_kernel(const float* __restrict__ bias,
                                                      const float* __restrict__ scale,
                                                      float* __restrict__ out) {
    extern __shared__ __align__(16) char smem[];
    uint32_t sb;
    asm("{ .reg .u64 t; cvta.to.shared.u64 t, %1; cvt.u32.u64 %0, t; }" : "=r"(sb) : "l"(smem));

    int tid  = threadIdx.x;
    int wid  = tid >> 5;
    int lane = tid & 31;
    int wm   = wid >> 1;        // 0..1 (64 rows)
    int wn   = wid & 1;         // 0..1 (64 cols)
    int bm   = blockIdx.y;
    int bn   = blockIdx.x;

    float acc[4][8][4];
    #pragma unroll
    for (int i = 0; i < 4; i++)
        #pragma unroll
        for (int j = 0; j < 8; j++)
            #pragma unroll
            for (int k = 0; k < 4; k++) acc[i][j][k] = 0.f;

    int r8 = lane & 7;
    int q  = lane >> 3;

    uint32_t aoff[4], boff[4];
    #pragma unroll
    for (int mi = 0; mi < 4; mi++)
        aoff[mi] = (uint32_t)((wm * 64 + mi * 16 + r8 + (q & 1) * 8) * LDA + (q >> 1) * 8) * 2;
    #pragma unroll
    for (int ni = 0; ni < 4; ni++)
        boff[ni] = (uint32_t)(((q & 1) * 8 + r8) * LDB + wn * 64 + ni * 16 + (q >> 1) * 8) * 2 + A_STAGE_B;

    uint32_t as_off[8], ag_off[8], bs_off[8], bg_off[8];
    #pragma unroll
    for (int i = 0; i < 8; i++) {
        int chunk = tid + i * 128;
        int arow = chunk >> 3, ac = chunk & 7;
        as_off[i] = (uint32_t)(arow * LDA + ac * 8) * 2;
        ag_off[i] = (uint32_t)arow * (D_Z * 2) + ac * 16;
        int brow = chunk >> 4, bc = chunk & 15;
        bs_off[i] = (uint32_t)(brow * LDB + bc * 8) * 2 + A_STAGE_B;
        bg_off[i] = (uint32_t)brow * (D_MODEL * 2) + bc * 16;
    }

    const char* Abase = (const char*)(g_zn + (size_t)(bm * BM) * D_Z);
    const char* Bbase = (const char*)(g_wb + (size_t)(bn * BN));

    // preload stages 0,1
    {
        #pragma unroll
        for (int i = 0; i < 8; i++) cp_async16(sb + as_off[i], Abase + ag_off[i]);
        #pragma unroll
        for (int i = 0; i < 8; i++) cp_async16(sb + bs_off[i], Bbase + bg_off[i]);
        CP_COMMIT();
        uint32_t s1 = sb + STAGE_B;
        const char* Ag = Abase + BK * 2;
        const char* Bg = Bbase + (size_t)BK * D_MODEL * 2;
        #pragma unroll
        for (int i = 0; i < 8; i++) cp_async16(s1 + as_off[i], Ag + ag_off[i]);
        #pragma unroll
        for (int i = 0; i < 8; i++) cp_async16(s1 + bs_off[i], Bg + bg_off[i]);
        CP_COMMIT();
    }

    const char* Agp = Abase + 2 * BK * 2;
    const char* Bgp = Bbase + (size_t)2 * BK * D_MODEL * 2;

    uint32_t abase = sb;
    const uint32_t send = sb + STAGES * STAGE_B;

    uint32_t af[2][4][4];
    uint32_t bf[2][16];

    // stage 0 ready -> load ks=0 fragments into buf 0
    CP_WAIT1();
    __syncthreads();
    load_frags(abase, af[0], bf[0], aoff, boff, 0, 0);

    for (int kt = 0; kt < KITERS; kt++) {
        bool do_refill = (kt + 2 < KITERS);
        uint32_t p = abase + 2 * STAGE_B;
        uint32_t pbase = (p >= send) ? p - STAGES * STAGE_B : p;

        uint32_t nbase = abase + STAGE_B;
        if (nbase >= send) nbase = sb;

        #pragma unroll
        for (int ks = 0; ks < 4; ks++) {
            int cur = ks & 1;

            // ---- spread refill of stage kt+2 across ks groups
            if (ks == 0 && do_refill) {
                #pragma unroll
                for (int i = 0; i < 4; i++) cp_async16(pbase + as_off[i], Agp + ag_off[i]);
                #pragma unroll
                for (int i = 0; i < 2; i++) cp_async16(pbase + bs_off[i], Bgp + bg_off[i]);
            }
            if (ks == 1 && do_refill) {
                #pragma unroll
                for (int i = 4; i < 8; i++) cp_async16(pbase + as_off[i], Agp + ag_off[i]);
                #pragma unroll
                for (int i = 2; i < 4; i++) cp_async16(pbase + bs_off[i], Bgp + bg_off[i]);
            }
            if (ks == 2) {
                if (do_refill) {
                    #pragma unroll
                    for (int i = 4; i < 8; i++) cp_async16(pbase + bs_off[i], Bgp + bg_off[i]);
                }
                CP_COMMIT();           // group for stage kt+2 (possibly empty)
            }

            // ---- fragment prefetch
            if (ks < 3) {
                load_frags(abase, af[cur ^ 1], bf[cur ^ 1], aoff, boff,
                           (uint32_t)((ks + 1) * 16) * 2,
                           (uint32_t)((ks + 1) * 16) * (LDB * 2));
            } else if (kt + 1 < KITERS) {
                CP_WAIT1();            // stage kt+1 resident (kt+2 may be in flight)
                __syncthreads();
                load_frags(nbase, af[cur ^ 1], bf[cur ^ 1], aoff, boff, 0, 0);
            }

            // ---- 32 MMAs on current buffer
            #pragma unroll
            for (int mi = 0; mi < 4; mi++)
                #pragma unroll
                for (int nb = 0; nb < 8; nb++)
                    mma_16816(acc[mi][nb], af[cur][mi],
                              bf[cur][(nb >> 1) * 4 + (nb & 1) * 2],
                              bf[cur][(nb >> 1) * 4 + (nb & 1) * 2 + 1]);
        }

        if (do_refill) {
            Agp += BK * 2;
            Bgp += (size_t)BK * D_MODEL * 2;
        }
        abase = nbase;
    }

    // epilogue: out = 3*tanh((acc + bias)*scale/3)
    float sc3 = scale[0] * (1.0f / 3.0f);
    int rr = lane >> 2;
    int cq = (lane & 3) * 2;

    #pragma unroll
    for (int nb = 0; nb < 8; nb++) {
        int col = bn * BN + wn * 64 + nb * 8 + cq;
        float2 bv = *(const float2*)(bias + col);
        #pragma unroll
        for (int mi = 0; mi < 4; mi++) {
            int row = bm * BM + wm * 64 + mi * 16 + rr;
            float2 o0, o1;
            o0.x = fast_tanh3(acc[mi][nb][0] + bv.x, sc3);
            o0.y = fast_tanh3(acc[mi][nb][1] + bv.y, sc3);
            o1.x = fast_tanh3(acc[mi][nb][2] + bv.x, sc3);
            o1.y = fast_tanh3(acc[mi][nb][3] + bv.y, sc3);
            *(float2*)(out + (size_t)row * D_MODEL + col)       = o0;
            *(float2*)(out + (size_t)(row + 8) * D_MODEL + col) = o1;
        }
    }
}

// ---------------------------------------------------------------- launch
extern "C" void kernel_launch(void* const* d_in, const int* in_sizes, int n_in,
                              void* d_out, int out_size) {
    const float* z     = (const float*)d_in[0];
    const float* gamma = (const float*)d_in[1];
    const float* beta  = (const float*)d_in[2];
    const float* W     = (const float*)d_in[3];
    const float* b     = (const float*)d_in[4];
    const float* scale = (const float*)d_in[5];
    float* out = (float*)d_out;
    (void)in_sizes; (void)n_in; (void)out_size;

    cudaFuncSetAttribute(gemm_kernel, cudaFuncAttributeMaxDynamicSharedMemorySize, SMEM_TOTAL);

    prep_kernel<<<LN_BLOCKS + WCONV_BLOCKS, 256>>>(z, gamma, beta, W);
    dim3 grid(D_MODEL / BN, M_ROWS / BM);   // (32, 128) = 4096 CTAs, 2/SM
    gemm_kernel<<<grid, 128, SMEM_TOTAL>>>(b, scale, out);
}

// round 14
// speedup vs baseline: 1.2838x; 1.0067x over previous
#include <cuda_runtime.h>
#include <cuda_fp16.h>
#include <cstdint>

// ---------------------------------------------------------------- constants
#define D_Z     1024
#define D_MODEL 4096
#define M_ROWS  16384
#define EPS     1e-5f

#define BM 128
#define BN 128
#define BK 64
#define KITERS (D_Z / BK)      // 16
#define STAGES 3

#define LDA 72                  // 64 + 8 pad (fp16): conflict-free ldmatrix
#define LDB 136                 // 128 + 8 pad
#define A_STAGE_B (BM * LDA * 2)          // 18432 B
#define B_STAGE_B (BK * LDB * 2)          // 17408 B
#define STAGE_B   (A_STAGE_B + B_STAGE_B) // 35840 B
#define SMEM_TOTAL (STAGES * STAGE_B)     // 107520 B -> 2 CTAs/SM

#define LN_BLOCKS   (M_ROWS / 8)          // 2048 (8 rows per block)
#define WCONV_BLOCKS 1024

// scratch (allocation-free rule: device globals)
__device__ __half g_zn[(size_t)M_ROWS * D_Z];     // LN output fp16 [M,K]
__device__ __half g_wb[(size_t)D_Z * D_MODEL];    // W fp16 [K,N]

// ---------------------------------------------------------------- K1: merged prep
__global__ __launch_bounds__(256) void prep_kernel(const float* __restrict__ z,
                                                   const float* __restrict__ gamma,
                                                   const float* __restrict__ beta,
                                                   const float* __restrict__ W) {
    int blk = blockIdx.x;
    int t   = threadIdx.x;

    if (blk >= LN_BLOCKS) {
        size_t base = (size_t)(blk - LN_BLOCKS) * 1024 + t;
        __half2* dst = (__half2*)g_wb;
        #pragma unroll
        for (int u = 0; u < 4; u++) {
            size_t i = base + (size_t)u * 256;
            float4 v = ((const float4*)W)[i];
            dst[i * 2 + 0] = __floats2half2_rn(v.x, v.y);
            dst[i * 2 + 1] = __floats2half2_rn(v.z, v.w);
        }
        return;
    }

    // ---- warp-per-row LayerNorm (no block barriers)
    int wid  = t >> 5;
    int lane = t & 31;
    int row  = blk * 8 + wid;

    const float4* zp = (const float4*)(z + (size_t)row * D_Z);
    float4 v[8];
    #pragma unroll
    for (int c = 0; c < 8; c++) v[c] = zp[lane + c * 32];

    float s = 0.f, ss = 0.f;
    #pragma unroll
    for (int c = 0; c < 8; c++) {
        s  += v[c].x + v[c].y + v[c].z + v[c].w;
        ss += v[c].x * v[c].x + v[c].y * v[c].y + v[c].z * v[c].z + v[c].w * v[c].w;
    }
    #pragma unroll
    for (int o = 16; o > 0; o >>= 1) {
        s  += __shfl_xor_sync(0xffffffffu, s, o);
        ss += __shfl_xor_sync(0xffffffffu, ss, o);
    }
    float mu   = s * (1.0f / D_Z);
    float var  = ss * (1.0f / D_Z) - mu * mu;
    float rstd = rsqrtf(var + EPS);

    const float4* gp = (const float4*)gamma;
    const float4* bp = (const float4*)beta;
    uint2* dst = (uint2*)(g_zn + (size_t)row * D_Z);
    #pragma unroll
    for (int c = 0; c < 8; c++) {
        float4 g = gp[lane + c * 32];
        float4 b = bp[lane + c * 32];
        float o0 = (v[c].x - mu) * rstd * g.x + b.x;
        float o1 = (v[c].y - mu) * rstd * g.y + b.y;
        float o2 = (v[c].z - mu) * rstd * g.z + b.z;
        float o3 = (v[c].w - mu) * rstd * g.w + b.w;
        __half2 h0 = __floats2half2_rn(o0, o1);
        __half2 h1 = __floats2half2_rn(o2, o3);
        uint2 pack;
        pack.x = *(uint32_t*)&h0;
        pack.y = *(uint32_t*)&h1;
        dst[lane + c * 32] = pack;
    }
}

// ---------------------------------------------------------------- PTX wrappers
__device__ __forceinline__ void ldmatrix_x4(uint32_t r[4], uint32_t addr) {
    asm volatile("ldmatrix.sync.aligned.m8n8.x4.shared.b16 {%0,%1,%2,%3}, [%4];\n"
                 : "=r"(r[0]), "=r"(r[1]), "=r"(r[2]), "=r"(r[3]) : "r"(addr));
}
__device__ __forceinline__ void ldmatrix_b(uint32_t& b00, uint32_t& b01,
                                           uint32_t& b10, uint32_t& b11, uint32_t addr) {
    asm volatile("ldmatrix.sync.aligned.m8n8.x4.trans.shared.b16 {%0,%1,%2,%3}, [%4];\n"
                 : "=r"(b00), "=r"(b01), "=r"(b10), "=r"(b11) : "r"(addr));
}
__device__ __forceinline__ void mma_16816(float c[4], const uint32_t a[4],
                                          uint32_t b0, uint32_t b1) {
    asm volatile("mma.sync.aligned.m16n8k16.row.col.f32.f16.f16.f32 "
                 "{%0,%1,%2,%3}, {%4,%5,%6,%7}, {%8,%9}, {%0,%1,%2,%3};\n"
                 : "+f"(c[0]), "+f"(c[1]), "+f"(c[2]), "+f"(c[3])
                 : "r"(a[0]), "r"(a[1]), "r"(a[2]), "r"(a[3]), "r"(b0), "r"(b1));
}
__device__ __forceinline__ void cp_async16(uint32_t dst, const void* src) {
    asm volatile("cp.async.cg.shared.global [%0], [%1], 16;\n" :: "r"(dst), "l"(src) : "memory");
}
#define CP_COMMIT() asm volatile("cp.async.commit_group;" ::: "memory")
#define CP_WAIT1()  asm volatile("cp.async.wait_group 1;" ::: "memory")

// fast tanh: tanh(t) = 1 - 2/(exp(2t)+1), rel err ~1e-6
__device__ __forceinline__ float fast_tanh3(float x, float sc3) {
    float t = x * sc3;
    float e;
    asm("ex2.approx.f32 %0, %1;" : "=f"(e) : "f"(t * 2.885390082f));
    float r;
    asm("rcp.approx.f32 %0, %1;" : "=f"(r) : "f"(e + 1.0f));
    return 3.0f * (1.0f - 2.0f * r);
}

// ---------------------------------------------------------------- K2: GEMM
__device__ __forceinline__ void load_frags(uint32_t base, uint32_t af[4][4], uint32_t bf[16],
                                           const uint32_t aoff[4], const uint32_t boff[4],
                                           uint32_t ko2, uint32_t kb) {
    #pragma unroll
    for (int mi = 0; mi < 4; mi++) ldmatrix_x4(af[mi], base + aoff[mi] + ko2);
    #pragma unroll
    for (int ni = 0; ni < 4; ni++)
        ldmatrix_b(bf[ni * 4 + 0], bf[ni * 4 + 1], bf[ni * 4 + 2], bf[ni * 4 + 3],
                   base + boff[ni] + kb);
}

__global__ __launch_bounds__(128, 2) void gemm_kernel(const float* __restrict__ bias,
                                                      const float* __restrict__ scale,
                                                      float* __restrict__ out) {
    extern __shared__ __align__(16) char smem[];
    uint32_t sb;
    asm("{ .reg .u64 t; cvta.to.shared.u64 t, %1; cvt.u32.u64 %0, t; }" : "=r"(sb) : "l"(smem));

    int tid  = threadIdx.x;
    int wid  = tid >> 5;
    int lane = tid & 31;
    int wm   = wid >> 1;        // 0..1 (64 rows)
    int wn   = wid & 1;         // 0..1 (64 cols)
    int bm   = blockIdx.y;
    int bn   = blockIdx.x;

    float acc[4][8][4];
    #pragma unroll
    for (int i = 0; i < 4; i++)
        #pragma unroll
        for (int j = 0; j < 8; j++)
            #pragma unroll
            for (int k = 0; k < 4; k++) acc[i][j][k] = 0.f;

    int r8 = lane & 7;
    int q  = lane >> 3;

    uint32_t aoff[4], boff[4];
    #pragma unroll
    for (int mi = 0; mi < 4; mi++)
        aoff[mi] = (uint32_t)((wm * 64 + mi * 16 + r8 + (q & 1) * 8) * LDA + (q >> 1) * 8) * 2;
    #pragma unroll
    for (int ni = 0; ni < 4; ni++)
        boff[ni] = (uint32_t)(((q & 1) * 8 + r8) * LDB + wn * 64 + ni * 16 + (q >> 1) * 8) * 2 + A_STAGE_B;

    uint32_t as_off[8], ag_off[8], bs_off[8], bg_off[8];
    #pragma unroll
    for (int i = 0; i < 8; i++) {
        int chunk = tid + i * 128;
        int arow = chunk >> 3, ac = chunk & 7;
        as_off[i] = (uint32_t)(arow * LDA + ac * 8) * 2;
        ag_off[i] = (uint32_t)arow * (D_Z * 2) + ac * 16;
        int brow = chunk >> 4, bc = chunk & 15;
        bs_off[i] = (uint32_t)(brow * LDB + bc * 8) * 2 + A_STAGE_B;
        bg_off[i] = (uint32_t)brow * (D_MODEL * 2) + bc * 16;
    }

    const char* Abase = (const char*)(g_zn + (size_t)(bm * BM) * D_Z);
    const char* Bbase = (const char*)(g_wb + (size_t)(bn * BN));

    // preload stages 0,1
    {
        #pragma unroll
        for (int i = 0; i < 8; i++) cp_async16(sb + as_off[i], Abase + ag_off[i]);
        #pragma unroll
        for (int i = 0; i < 8; i++) cp_async16(sb + bs_off[i], Bbase + bg_off[i]);
        CP_COMMIT();
        uint32_t s1 = sb + STAGE_B;
        const char* Ag = Abase + BK * 2;
        const char* Bg = Bbase + (size_t)BK * D_MODEL * 2;
        #pragma unroll
        for (int i = 0; i < 8; i++) cp_async16(s1 + as_off[i], Ag + ag_off[i]);
        #pragma unroll
        for (int i = 0; i < 8; i++) cp_async16(s1 + bs_off[i], Bg + bg_off[i]);
        CP_COMMIT();
    }

    const char* Agp = Abase + 2 * BK * 2;
    const char* Bgp = Bbase + (size_t)2 * BK * D_MODEL * 2;

    uint32_t abase = sb;
    const uint32_t send = sb + STAGES * STAGE_B;

    uint32_t af[2][4][4];
    uint32_t bf[2][16];

    // stage 0 ready -> load ks=0 fragments into buf 0
    CP_WAIT1();
    __syncthreads();
    load_frags(abase, af[0], bf[0], aoff, boff, 0, 0);

    for (int kt = 0; kt < KITERS; kt++) {
        bool do_refill = (kt + 2 < KITERS);
        uint32_t p = abase + 2 * STAGE_B;
        uint32_t pbase = (p >= send) ? p - STAGES * STAGE_B : p;

        uint32_t nbase = abase + STAGE_B;
        if (nbase >= send) nbase = sb;

        #pragma unroll
        for (int ks = 0; ks < 4; ks++) {
            int cur = ks & 1;

            // fragment prefetch FIRST (never queued behind cp.async in LSU)
            if (ks < 3) {
                load_frags(abase, af[cur ^ 1], bf[cur ^ 1], aoff, boff,
                           (uint32_t)((ks + 1) * 16) * 2,
                           (uint32_t)((ks + 1) * 16) * (LDB * 2));
            }

            // refill of stage kt+2 spread over ks1..ks3 (ks0 kept load-free)
            if (ks == 1 && do_refill) {
                #pragma unroll
                for (int i = 0; i < 4; i++) cp_async16(pbase + as_off[i], Agp + ag_off[i]);
                #pragma unroll
                for (int i = 0; i < 2; i++) cp_async16(pbase + bs_off[i], Bgp + bg_off[i]);
            }
            if (ks == 2 && do_refill) {
                #pragma unroll
                for (int i = 4; i < 8; i++) cp_async16(pbase + as_off[i], Agp + ag_off[i]);
                #pragma unroll
                for (int i = 2; i < 4; i++) cp_async16(pbase + bs_off[i], Bgp + bg_off[i]);
            }

            if (ks < 3) {
                // full MMA group
                #pragma unroll
                for (int mi = 0; mi < 4; mi++)
                    #pragma unroll
                    for (int nb = 0; nb < 8; nb++)
                        mma_16816(acc[mi][nb], af[cur][mi],
                                  bf[cur][(nb >> 1) * 4 + (nb & 1) * 2],
                                  bf[cur][(nb >> 1) * 4 + (nb & 1) * 2 + 1]);
            } else {
                // last refill chunk + commit (group for stage kt+2, possibly empty)
                if (do_refill) {
                    #pragma unroll
                    for (int i = 4; i < 8; i++) cp_async16(pbase + bs_off[i], Bgp + bg_off[i]);
                }
                CP_COMMIT();

                // first half of ks3 MMAs: keeps tensor pipe fed through the barrier
                #pragma unroll
                for (int mi = 0; mi < 2; mi++)
                    #pragma unroll
                    for (int nb = 0; nb < 8; nb++)
                        mma_16816(acc[mi][nb], af[cur][mi],
                                  bf[cur][(nb >> 1) * 4 + (nb & 1) * 2],
                                  bf[cur][(nb >> 1) * 4 + (nb & 1) * 2 + 1]);

                if (kt + 1 < KITERS) {
                    CP_WAIT1();            // stage kt+1 resident (kt+2 may be in flight)
                    __syncthreads();
                    load_frags(nbase, af[cur ^ 1], bf[cur ^ 1], aoff, boff, 0, 0);
                }

                // second half of ks3 MMAs
                #pragma unroll
                for (int mi = 2; mi < 4; mi++)
                    #pragma unroll
                    for (int nb = 0; nb < 8; nb++)
                        mma_16816(acc[mi][nb], af[cur][mi],
                                  bf[cur][(nb >> 1) * 4 + (nb & 1) * 2],
                                  bf[cur][(nb >> 1) * 4 + (nb & 1) * 2 + 1]);
            }
        }

        if (do_refill) {
            Agp += BK * 2;
            Bgp += (size_t)BK * D_MODEL * 2;
        }
        abase = nbase;
    }

    // epilogue: out = 3*tanh((acc + bias)*scale/3)
    float sc3 = scale[0] * (1.0f / 3.0f);
    int rr = lane >> 2;
    int cq = (lane & 3) * 2;

    #pragma unroll
    for (int nb = 0; nb < 8; nb++) {
        int col = bn * BN + wn * 64 + nb * 8 + cq;
        float2 bv = *(const float2*)(bias + col);
        #pragma unroll
        for (int mi = 0; mi < 4; mi++) {
            int row = bm * BM + wm * 64 + mi * 16 + rr;
            float2 o0, o1;
            o0.x = fast_tanh3(acc[mi][nb][0] + bv.x, sc3);
            o0.y = fast_tanh3(acc[mi][nb][1] + bv.y, sc3);
            o1.x = fast_tanh3(acc[mi][nb][2] + bv.x, sc3);
            o1.y = fast_tanh3(acc[mi][nb][3] + bv.y, sc3);
            *(float2*)(out + (size_t)row * D_MODEL + col)       = o0;
            *(float2*)(out + (size_t)(row + 8) * D_MODEL + col) = o1;
        }
    }
}

// ---------------------------------------------------------------- launch
extern "C" void kernel_launch(void* const* d_in, const int* in_sizes, int n_in,
                              void* d_out, int out_size) {
    const float* z     = (const float*)d_in[0];
    const float* gamma = (const float*)d_in[1];
    const float* beta  = (const float*)d_in[2];
    const float* W     = (const float*)d_in[3];
    const float* b     = (const float*)d_in[4];
    const float* scale = (const float*)d_in[5];
    float* out = (float*)d_out;
    (void)in_sizes; (void)n_in; (void)out_size;

    cudaFuncSetAttribute(gemm_kernel, cudaFuncAttributeMaxDynamicSharedMemorySize, SMEM_TOTAL);

    prep_kernel<<<LN_BLOCKS + WCONV_BLOCKS, 256>>>(z, gamma, beta, W);
    dim3 grid(D_MODEL / BN, M_ROWS / BM);   // (32, 128) = 4096 CTAs, 2/SM
    gemm_kernel<<<grid, 128, SMEM_TOTAL>>>(b, scale, out);
}